// round 10
// baseline (speedup 1.0000x reference)
#include <cuda_runtime.h>
#include <cuda_bf16.h>
#include <cstdint>

// ---------------------------------------------------------------------------
// Swin window attention: B_=2048, N=49, H=16, D=32, C=512, nW=64, fp32.
// Split-bf16 HMMA GEMM (R9 winner, unchanged: 3-stage ring, 1 sync/epoch,
// chunk-rotated 64B rows, 2 CTA/SM) + packed-f32x2 fused attention.
// ---------------------------------------------------------------------------
#define B_TOT   2048
#define NTOK    49
#define NHEAD   16
#define HDIM    32
#define CDIM    512
#define NWIN    64
#define QK_SCALE 0.17677669529663687f
#define M_ROWS  (B_TOT * NTOK)          // 100352 = 784 * 128

__device__ float          g_qkv[(size_t)M_ROWS * 3 * CDIM];
__device__ __nv_bfloat16  g_xh [(size_t)M_ROWS * CDIM];
__device__ __nv_bfloat16  g_xl [(size_t)M_ROWS * CDIM];
__device__ __nv_bfloat16  g_aoh[(size_t)M_ROWS * CDIM];
__device__ __nv_bfloat16  g_aol[(size_t)M_ROWS * CDIM];
__device__ __nv_bfloat16  g_wqh[3 * CDIM * CDIM];
__device__ __nv_bfloat16  g_wql[3 * CDIM * CDIM];
__device__ __nv_bfloat16  g_wph[CDIM * CDIM];
__device__ __nv_bfloat16  g_wpl[CDIM * CDIM];

// ---------------------------------------------------------------------------
__device__ __forceinline__ uint32_t smem_u32(const void* p) {
    uint32_t a;
    asm("{ .reg .u64 t; cvta.to.shared.u64 t, %1; cvt.u32.u64 %0, t; }"
        : "=r"(a) : "l"(p));
    return a;
}

__device__ __forceinline__ void cvt_pair(float x, float y, uint32_t& hp, uint32_t& lp) {
    unsigned short h0 = __bfloat16_as_ushort(__float2bfloat16_rn(x));
    unsigned short h1 = __bfloat16_as_ushort(__float2bfloat16_rn(y));
    hp = (uint32_t)h0 | ((uint32_t)h1 << 16);
    float l0 = x - __uint_as_float((uint32_t)h0 << 16);
    float l1 = y - __uint_as_float((uint32_t)h1 << 16);
    asm("cvt.rn.bf16x2.f32 %0, %1, %2;" : "=r"(lp) : "f"(l1), "f"(l0));
}

#define LDSM4(r, addr) \
    asm volatile("ldmatrix.sync.aligned.m8n8.x4.shared.b16 {%0,%1,%2,%3}, [%4];" \
        : "=r"((r)[0]), "=r"((r)[1]), "=r"((r)[2]), "=r"((r)[3]) : "r"(addr))

#define MMA16816(d, a, b0, b1) \
    asm volatile("mma.sync.aligned.m16n8k16.row.col.f32.bf16.bf16.f32 " \
        "{%0,%1,%2,%3}, {%4,%5,%6,%7}, {%8,%9}, {%0,%1,%2,%3};" \
        : "+f"((d)[0]), "+f"((d)[1]), "+f"((d)[2]), "+f"((d)[3]) \
        : "r"((a)[0]), "r"((a)[1]), "r"((a)[2]), "r"((a)[3]), "r"(b0), "r"(b1))

#define CP16(saddr, gaddr) \
    asm volatile("cp.async.cg.shared.global [%0], [%1], 16;" :: "r"(saddr), "l"(gaddr))
#define CP_COMMIT() asm volatile("cp.async.commit_group;" ::: "memory")
#define CP_WAIT(n)  asm volatile("cp.async.wait_group %0;" :: "n"(n) : "memory")

// packed fp32x2 fma: d += a * b (element-wise on 2 lanes)
#define FMA2(d, a, b) \
    asm("fma.rn.f32x2 %0, %1, %2, %0;" : "+l"(d) : "l"(a), "l"(b))
#define UNPACK2(lo, hi, v) \
    asm("mov.b64 {%0, %1}, %2;" : "=f"(lo), "=f"(hi) : "l"(v))

// ---------------------------------------------------------------------------
__global__ void split_bf16_kernel(const float4* __restrict__ src,
                                  uint2* __restrict__ dh, uint2* __restrict__ dl,
                                  int n4)
{
    int i = blockIdx.x * blockDim.x + threadIdx.x;
    if (i < n4) {
        float4 v = src[i];
        uint32_t h0, l0, h1, l1;
        cvt_pair(v.x, v.y, h0, l0);
        cvt_pair(v.z, v.w, h1, l1);
        dh[i] = make_uint2(h0, h1);
        dl[i] = make_uint2(l0, l1);
    }
}

// ---------------------------------------------------------------------------
// HMMA split-bf16 GEMM (R9 winner, unchanged).
// ---------------------------------------------------------------------------
#define TILE_SZ   8192             // 128 rows * 64B
#define STAGE_SZ  32768            // AH AL BH BL
#define SMEM_GEMM 98304            // 3 stages

__global__ __launch_bounds__(256, 2)
void hmma_gemm(const __nv_bfloat16* __restrict__ Ah, const __nv_bfloat16* __restrict__ Al,
               const __nv_bfloat16* __restrict__ Bh, const __nv_bfloat16* __restrict__ Bl,
               const float* __restrict__ bias, float* __restrict__ C,
               int N, int K)
{
    extern __shared__ char sm[];
    const uint32_t sb = smem_u32(sm);

    const int tid = threadIdx.x;
    const int wid = tid >> 5, lid = tid & 31;
    const int warp_m = wid & 1;
    const int warp_n = wid >> 1;
    const int m0 = blockIdx.y * 128;
    const int n0 = blockIdx.x * 128;

    const __nv_bfloat16* gbase[4] = {
        Ah + (size_t)m0 * K, Al + (size_t)m0 * K,
        Bh + (size_t)n0 * K, Bl + (size_t)n0 * K };

    const uint32_t aRowL = (uint32_t)(warp_m * 64 + (lid & 15));
    const uint32_t ac    = (uint32_t)(lid >> 4);
    const uint32_t arot  = (aRowL >> 1) & 3;
    const uint32_t aO[2] = { aRowL * 64 + ((ac + arot) & 3) * 16,
                             aRowL * 64 + ((ac + 2 + arot) & 3) * 16 };
    const uint32_t bRowL = (uint32_t)(warp_n * 32 + ((lid >> 4) << 3) + (lid & 7));
    const uint32_t bc    = (uint32_t)((lid >> 3) & 1);
    const uint32_t brot  = (bRowL >> 1) & 3;
    const uint32_t bO[2] = { bRowL * 64 + ((bc + brot) & 3) * 16,
                             bRowL * 64 + ((bc + 2 + brot) & 3) * 16 };

    float acc[4][4][4];
#pragma unroll
    for (int i = 0; i < 4; i++)
#pragma unroll
        for (int j = 0; j < 4; j++)
#pragma unroll
            for (int e = 0; e < 4; e++) acc[i][j][e] = 0.f;

    const int iters = K >> 5;

#define ISSUE_STAGE(it) do {                                                  \
        const int kblk = (it) * 32;                                           \
        const uint32_t stb = sb + ((it) % 3) * STAGE_SZ;                      \
        _Pragma("unroll")                                                     \
        for (int s = 0; s < 8; s++) {                                         \
            const int id   = tid + s * 256;                                   \
            const int tile = id >> 9;                                         \
            const int row  = (id >> 2) & 127;                                 \
            const int c    = id & 3;                                          \
            const int cc   = (c + ((row >> 1) & 3)) & 3;                      \
            CP16(stb + tile * TILE_SZ + row * 64 + cc * 16,                   \
                 gbase[tile] + (size_t)row * K + kblk + c * 8);               \
        }                                                                     \
    } while (0)

    ISSUE_STAGE(0); CP_COMMIT();
    ISSUE_STAGE(1); CP_COMMIT();

    for (int i = 0; i < iters; i++) {
        if (i + 1 < iters) CP_WAIT(1); else CP_WAIT(0);
        __syncthreads();
        if (i + 2 < iters) { ISSUE_STAGE(i + 2); CP_COMMIT(); }

        const uint32_t st  = sb + (i % 3) * STAGE_SZ;
        const uint32_t aHi = st;
        const uint32_t aLo = st + TILE_SZ;
        const uint32_t bHi = st + 2 * TILE_SZ;
        const uint32_t bLo = st + 3 * TILE_SZ;

#pragma unroll
        for (int ks = 0; ks < 2; ks++) {
            uint32_t bh[2][4], bl[2][4];
            LDSM4(bh[0], bHi + bO[ks]);
            LDSM4(bh[1], bHi + bO[ks] + 16 * 64);
            LDSM4(bl[0], bLo + bO[ks]);
            LDSM4(bl[1], bLo + bO[ks] + 16 * 64);
#pragma unroll
            for (int mi = 0; mi < 4; mi++) {
                uint32_t ah[4], al[4];
                LDSM4(ah, aHi + aO[ks] + mi * (16 * 64));
                LDSM4(al, aLo + aO[ks] + mi * (16 * 64));
#pragma unroll
                for (int nj = 0; nj < 4; nj++) {
                    const uint32_t* bph = bh[nj >> 1] + ((nj & 1) << 1);
                    const uint32_t* bpl = bl[nj >> 1] + ((nj & 1) << 1);
                    MMA16816(acc[mi][nj], ah, bph[0], bph[1]);
                    MMA16816(acc[mi][nj], ah, bpl[0], bpl[1]);
                    MMA16816(acc[mi][nj], al, bph[0], bph[1]);
                }
            }
        }
    }
#undef ISSUE_STAGE

    const int l4 = lid >> 2;
    const int lc = (lid & 3) * 2;
#pragma unroll
    for (int mi = 0; mi < 4; mi++) {
        const int row = m0 + warp_m * 64 + mi * 16 + l4;
#pragma unroll
        for (int nj = 0; nj < 4; nj++) {
            const int col = n0 + warp_n * 32 + nj * 8 + lc;
            const float b0 = bias[col], b1 = bias[col + 1];
            float2 v0 = make_float2(acc[mi][nj][0] + b0, acc[mi][nj][1] + b1);
            float2 v1 = make_float2(acc[mi][nj][2] + b0, acc[mi][nj][3] + b1);
            *(float2*)(C + (size_t)row * N + col)       = v0;
            *(float2*)(C + (size_t)(row + 8) * N + col) = v1;
        }
    }
}

// ---------------------------------------------------------------------------
// Fused window attention with packed fma.rn.f32x2 math.
//   phase1: acc packed over d-pairs; q/k loaded as ulonglong2 (free packing)
//   phase2: acc packed over m-pairs; V in interleaved vsp[m2][2d+(m&1)]
//           layout so P (contiguous sc) and V both load as packed u64.
// ---------------------------------------------------------------------------
#define SCPAD 68
#define VSPR  66    // vsp row stride in floats (33 float2)

__global__ __launch_bounds__(128)
void window_attn_kernel(const float* __restrict__ qkv,
                        const float* __restrict__ mask,
                        const float* __restrict__ rpb,
                        __nv_bfloat16* __restrict__ aoh,
                        __nv_bfloat16* __restrict__ aol)
{
    const int b = blockIdx.x >> 4;
    const int h = blockIdx.x & 15;
    const int tid = threadIdx.x;
    const int wid = tid >> 5, lid = tid & 31;

    __shared__ float qs[56][36];
    __shared__ float ks[64][36];
    __shared__ float vsp[32][VSPR];   // (m2, 2d + (m&1)) interleaved V
    __shared__ float sc[56][SCPAD];

    const size_t base = (size_t)b * NTOK * (3 * CDIM) + h * HDIM;
    for (int idx = tid; idx < NTOK * HDIM; idx += 128) {
        const int n = idx >> 5, d = idx & 31;
        const size_t off = base + (size_t)n * (3 * CDIM) + d;
        qs[n][d] = qkv[off] * QK_SCALE;
        ks[n][d] = qkv[off + CDIM];
        vsp[n >> 1][2 * d + (n & 1)] = qkv[off + 2 * CDIM];
    }
    for (int idx = tid; idx < 15 * HDIM; idx += 128) {
        const int n = NTOK + (idx >> 5), d = idx & 31;
        if (n < 56) qs[n][d] = 0.f;
        ks[n][d] = 0.f;
        vsp[n >> 1][2 * d + (n & 1)] = 0.f;
    }
    __syncthreads();

    // ---- phase1: scores, packed over d-pairs ----
    const float* mrow = mask + (size_t)(b & (NWIN - 1)) * NTOK * NTOK;
    {
        const int nt = tid & 7;
        const int mt = tid >> 3;
        unsigned long long a2[7][4];
#pragma unroll
        for (int i = 0; i < 7; i++)
#pragma unroll
            for (int j = 0; j < 4; j++) a2[i][j] = 0ull;

#pragma unroll
        for (int d4 = 0; d4 < 8; d4++) {
            ulonglong2 k2[4];
#pragma unroll
            for (int j = 0; j < 4; j++)
                k2[j] = *(ulonglong2*)&ks[mt * 4 + j][d4 * 4];
#pragma unroll
            for (int i = 0; i < 7; i++) {
                ulonglong2 q2 = *(ulonglong2*)&qs[nt * 7 + i][d4 * 4];
#pragma unroll
                for (int j = 0; j < 4; j++) {
                    FMA2(a2[i][j], q2.x, k2[j].x);
                    FMA2(a2[i][j], q2.y, k2[j].y);
                }
            }
        }
#pragma unroll
        for (int i = 0; i < 7; i++) {
            const int n = nt * 7 + i;
#pragma unroll
            for (int j = 0; j < 4; j++) {
                const int m = mt * 4 + j;
                float v;
                if (n < NTOK && m < NTOK) {
                    float lo, hi;
                    UNPACK2(lo, hi, a2[i][j]);
                    const int ridx = (n / 7 - m / 7 + 6) * 13 + (n % 7 - m % 7 + 6);
                    v = lo + hi + rpb[ridx * NHEAD + h] + mrow[n * NTOK + m];
                } else {
                    v = (n < NTOK) ? -3.0e38f : 0.f;
                }
                sc[n][m] = v;
            }
        }
    }
    __syncthreads();

    // ---- softmax: warp per row over 64 cols ----
    for (int r = wid; r < NTOK; r += 4) {
        float v0 = sc[r][lid];
        float v1 = sc[r][lid + 32];
        float mx = fmaxf(v0, v1);
#pragma unroll
        for (int o = 16; o; o >>= 1) mx = fmaxf(mx, __shfl_xor_sync(~0u, mx, o));
        float e0 = __expf(v0 - mx);
        float e1 = __expf(v1 - mx);
        float s = e0 + e1;
#pragma unroll
        for (int o = 16; o; o >>= 1) s += __shfl_xor_sync(~0u, s, o);
        const float inv = 1.f / s;
        sc[r][lid] = e0 * inv;
        sc[r][lid + 32] = e1 * inv;
    }
    __syncthreads();

    // ---- phase2: out = P @ V, packed over m-pairs ----
    {
        const int dp = tid & 15;         // d0 = 2dp, d1 = 2dp+1
        const int nb = tid >> 4;         // rows nb + 8i
        unsigned long long ac2[7][2];
#pragma unroll
        for (int i = 0; i < 7; i++) { ac2[i][0] = 0ull; ac2[i][1] = 0ull; }

#pragma unroll
        for (int m4 = 0; m4 < 16; m4++) {
            // V m-pairs for m2 = 2*m4 (vm0*) and m2 = 2*m4+1 (vm1*)
            unsigned long long v00 = *(unsigned long long*)&vsp[m4 * 2][4 * dp];
            unsigned long long v01 = *(unsigned long long*)&vsp[m4 * 2][4 * dp + 2];
            unsigned long long v10 = *(unsigned long long*)&vsp[m4 * 2 + 1][4 * dp];
            unsigned long long v11 = *(unsigned long long*)&vsp[m4 * 2 + 1][4 * dp + 2];
#pragma unroll
            for (int i = 0; i < 7; i++) {
                ulonglong2 s2 = *(ulonglong2*)&sc[nb + 8 * i][4 * m4];
                FMA2(ac2[i][0], s2.x, v00);
                FMA2(ac2[i][0], s2.y, v10);
                FMA2(ac2[i][1], s2.x, v01);
                FMA2(ac2[i][1], s2.y, v11);
            }
        }
#pragma unroll
        for (int i = 0; i < 7; i++) {
            const int n = nb + 8 * i;
            if (n < NTOK) {
                float a0, a1, b0, b1;
                UNPACK2(a0, a1, ac2[i][0]);
                UNPACK2(b0, b1, ac2[i][1]);
                const size_t o = (size_t)(b * NTOK + n) * CDIM + h * HDIM + dp * 2;
                uint32_t hp, lp;
                cvt_pair(a0 + a1, b0 + b1, hp, lp);
                *(uint32_t*)(aoh + o) = hp;
                *(uint32_t*)(aol + o) = lp;
            }
        }
    }
}

// ---------------------------------------------------------------------------
extern "C" void kernel_launch(void* const* d_in, const int* in_sizes, int n_in,
                              void* d_out, int out_size)
{
    const float* x      = (const float*)d_in[0];
    const float* mask   = (const float*)d_in[1];
    const float* rpb    = (const float*)d_in[2];
    const float* qkv_w  = (const float*)d_in[3];
    const float* qkv_b  = (const float*)d_in[4];
    const float* proj_w = (const float*)d_in[5];
    const float* proj_b = (const float*)d_in[6];
    float* out = (float*)d_out;

    float *qkv_ptr = nullptr;
    __nv_bfloat16 *xh, *xl, *aoh, *aol, *wqh, *wql, *wph, *wpl;
    cudaGetSymbolAddress((void**)&qkv_ptr, g_qkv);
    cudaGetSymbolAddress((void**)&xh,  g_xh);
    cudaGetSymbolAddress((void**)&xl,  g_xl);
    cudaGetSymbolAddress((void**)&aoh, g_aoh);
    cudaGetSymbolAddress((void**)&aol, g_aol);
    cudaGetSymbolAddress((void**)&wqh, g_wqh);
    cudaGetSymbolAddress((void**)&wql, g_wql);
    cudaGetSymbolAddress((void**)&wph, g_wph);
    cudaGetSymbolAddress((void**)&wpl, g_wpl);

    static bool cfg = false;
    if (!cfg) {
        cudaFuncSetAttribute(hmma_gemm, cudaFuncAttributeMaxDynamicSharedMemorySize,
                             SMEM_GEMM);
        cfg = true;
    }

    {
        int n4 = (M_ROWS * CDIM) / 4;
        split_bf16_kernel<<<(n4 + 255) / 256, 256>>>(
            (const float4*)x, (uint2*)xh, (uint2*)xl, n4);
        n4 = (3 * CDIM * CDIM) / 4;
        split_bf16_kernel<<<(n4 + 255) / 256, 256>>>(
            (const float4*)qkv_w, (uint2*)wqh, (uint2*)wql, n4);
        n4 = (CDIM * CDIM) / 4;
        split_bf16_kernel<<<(n4 + 255) / 256, 256>>>(
            (const float4*)proj_w, (uint2*)wph, (uint2*)wpl, n4);
    }

    hmma_gemm<<<dim3((3 * CDIM) / 128, M_ROWS / 128), 256, SMEM_GEMM>>>(
        xh, xl, wqh, wql, qkv_b, qkv_ptr, 3 * CDIM, CDIM);

    window_attn_kernel<<<B_TOT * NHEAD, 128>>>(qkv_ptr, mask, rpb, aoh, aol);

    hmma_gemm<<<dim3(CDIM / 128, M_ROWS / 128), 256, SMEM_GEMM>>>(
        aoh, aol, wph, wpl, proj_b, out, CDIM, CDIM);
}

// round 11
// speedup vs baseline: 1.0739x; 1.0739x over previous
#include <cuda_runtime.h>
#include <cuda_bf16.h>
#include <cstdint>

// ---------------------------------------------------------------------------
// Swin window attention: B_=2048, N=49, H=16, D=32, C=512, nW=64, fp32.
// Split-bf16 HMMA GEMM (R9 winner, unchanged) + 256-thread fused attention
// (R9 math, halved per-thread tiles, 2x warps for latency hiding).
// ---------------------------------------------------------------------------
#define B_TOT   2048
#define NTOK    49
#define NHEAD   16
#define HDIM    32
#define CDIM    512
#define NWIN    64
#define QK_SCALE 0.17677669529663687f
#define M_ROWS  (B_TOT * NTOK)          // 100352 = 784 * 128

__device__ float          g_qkv[(size_t)M_ROWS * 3 * CDIM];
__device__ __nv_bfloat16  g_xh [(size_t)M_ROWS * CDIM];
__device__ __nv_bfloat16  g_xl [(size_t)M_ROWS * CDIM];
__device__ __nv_bfloat16  g_aoh[(size_t)M_ROWS * CDIM];
__device__ __nv_bfloat16  g_aol[(size_t)M_ROWS * CDIM];
__device__ __nv_bfloat16  g_wqh[3 * CDIM * CDIM];
__device__ __nv_bfloat16  g_wql[3 * CDIM * CDIM];
__device__ __nv_bfloat16  g_wph[CDIM * CDIM];
__device__ __nv_bfloat16  g_wpl[CDIM * CDIM];

// ---------------------------------------------------------------------------
__device__ __forceinline__ uint32_t smem_u32(const void* p) {
    uint32_t a;
    asm("{ .reg .u64 t; cvta.to.shared.u64 t, %1; cvt.u32.u64 %0, t; }"
        : "=r"(a) : "l"(p));
    return a;
}

__device__ __forceinline__ void cvt_pair(float x, float y, uint32_t& hp, uint32_t& lp) {
    unsigned short h0 = __bfloat16_as_ushort(__float2bfloat16_rn(x));
    unsigned short h1 = __bfloat16_as_ushort(__float2bfloat16_rn(y));
    hp = (uint32_t)h0 | ((uint32_t)h1 << 16);
    float l0 = x - __uint_as_float((uint32_t)h0 << 16);
    float l1 = y - __uint_as_float((uint32_t)h1 << 16);
    asm("cvt.rn.bf16x2.f32 %0, %1, %2;" : "=r"(lp) : "f"(l1), "f"(l0));
}

#define LDSM4(r, addr) \
    asm volatile("ldmatrix.sync.aligned.m8n8.x4.shared.b16 {%0,%1,%2,%3}, [%4];" \
        : "=r"((r)[0]), "=r"((r)[1]), "=r"((r)[2]), "=r"((r)[3]) : "r"(addr))

#define MMA16816(d, a, b0, b1) \
    asm volatile("mma.sync.aligned.m16n8k16.row.col.f32.bf16.bf16.f32 " \
        "{%0,%1,%2,%3}, {%4,%5,%6,%7}, {%8,%9}, {%0,%1,%2,%3};" \
        : "+f"((d)[0]), "+f"((d)[1]), "+f"((d)[2]), "+f"((d)[3]) \
        : "r"((a)[0]), "r"((a)[1]), "r"((a)[2]), "r"((a)[3]), "r"(b0), "r"(b1))

#define CP16(saddr, gaddr) \
    asm volatile("cp.async.cg.shared.global [%0], [%1], 16;" :: "r"(saddr), "l"(gaddr))
#define CP_COMMIT() asm volatile("cp.async.commit_group;" ::: "memory")
#define CP_WAIT(n)  asm volatile("cp.async.wait_group %0;" :: "n"(n) : "memory")

// ---------------------------------------------------------------------------
__global__ void split_bf16_kernel(const float4* __restrict__ src,
                                  uint2* __restrict__ dh, uint2* __restrict__ dl,
                                  int n4)
{
    int i = blockIdx.x * blockDim.x + threadIdx.x;
    if (i < n4) {
        float4 v = src[i];
        uint32_t h0, l0, h1, l1;
        cvt_pair(v.x, v.y, h0, l0);
        cvt_pair(v.z, v.w, h1, l1);
        dh[i] = make_uint2(h0, h1);
        dl[i] = make_uint2(l0, l1);
    }
}

// ---------------------------------------------------------------------------
// HMMA split-bf16 GEMM (R9 winner, unchanged).
// ---------------------------------------------------------------------------
#define TILE_SZ   8192             // 128 rows * 64B
#define STAGE_SZ  32768            // AH AL BH BL
#define SMEM_GEMM 98304            // 3 stages

__global__ __launch_bounds__(256, 2)
void hmma_gemm(const __nv_bfloat16* __restrict__ Ah, const __nv_bfloat16* __restrict__ Al,
               const __nv_bfloat16* __restrict__ Bh, const __nv_bfloat16* __restrict__ Bl,
               const float* __restrict__ bias, float* __restrict__ C,
               int N, int K)
{
    extern __shared__ char sm[];
    const uint32_t sb = smem_u32(sm);

    const int tid = threadIdx.x;
    const int wid = tid >> 5, lid = tid & 31;
    const int warp_m = wid & 1;
    const int warp_n = wid >> 1;
    const int m0 = blockIdx.y * 128;
    const int n0 = blockIdx.x * 128;

    const __nv_bfloat16* gbase[4] = {
        Ah + (size_t)m0 * K, Al + (size_t)m0 * K,
        Bh + (size_t)n0 * K, Bl + (size_t)n0 * K };

    const uint32_t aRowL = (uint32_t)(warp_m * 64 + (lid & 15));
    const uint32_t ac    = (uint32_t)(lid >> 4);
    const uint32_t arot  = (aRowL >> 1) & 3;
    const uint32_t aO[2] = { aRowL * 64 + ((ac + arot) & 3) * 16,
                             aRowL * 64 + ((ac + 2 + arot) & 3) * 16 };
    const uint32_t bRowL = (uint32_t)(warp_n * 32 + ((lid >> 4) << 3) + (lid & 7));
    const uint32_t bc    = (uint32_t)((lid >> 3) & 1);
    const uint32_t brot  = (bRowL >> 1) & 3;
    const uint32_t bO[2] = { bRowL * 64 + ((bc + brot) & 3) * 16,
                             bRowL * 64 + ((bc + 2 + brot) & 3) * 16 };

    float acc[4][4][4];
#pragma unroll
    for (int i = 0; i < 4; i++)
#pragma unroll
        for (int j = 0; j < 4; j++)
#pragma unroll
            for (int e = 0; e < 4; e++) acc[i][j][e] = 0.f;

    const int iters = K >> 5;

#define ISSUE_STAGE(it) do {                                                  \
        const int kblk = (it) * 32;                                           \
        const uint32_t stb = sb + ((it) % 3) * STAGE_SZ;                      \
        _Pragma("unroll")                                                     \
        for (int s = 0; s < 8; s++) {                                         \
            const int id   = tid + s * 256;                                   \
            const int tile = id >> 9;                                         \
            const int row  = (id >> 2) & 127;                                 \
            const int c    = id & 3;                                          \
            const int cc   = (c + ((row >> 1) & 3)) & 3;                      \
            CP16(stb + tile * TILE_SZ + row * 64 + cc * 16,                   \
                 gbase[tile] + (size_t)row * K + kblk + c * 8);               \
        }                                                                     \
    } while (0)

    ISSUE_STAGE(0); CP_COMMIT();
    ISSUE_STAGE(1); CP_COMMIT();

    for (int i = 0; i < iters; i++) {
        if (i + 1 < iters) CP_WAIT(1); else CP_WAIT(0);
        __syncthreads();
        if (i + 2 < iters) { ISSUE_STAGE(i + 2); CP_COMMIT(); }

        const uint32_t st  = sb + (i % 3) * STAGE_SZ;
        const uint32_t aHi = st;
        const uint32_t aLo = st + TILE_SZ;
        const uint32_t bHi = st + 2 * TILE_SZ;
        const uint32_t bLo = st + 3 * TILE_SZ;

#pragma unroll
        for (int ks = 0; ks < 2; ks++) {
            uint32_t bh[2][4], bl[2][4];
            LDSM4(bh[0], bHi + bO[ks]);
            LDSM4(bh[1], bHi + bO[ks] + 16 * 64);
            LDSM4(bl[0], bLo + bO[ks]);
            LDSM4(bl[1], bLo + bO[ks] + 16 * 64);
#pragma unroll
            for (int mi = 0; mi < 4; mi++) {
                uint32_t ah[4], al[4];
                LDSM4(ah, aHi + aO[ks] + mi * (16 * 64));
                LDSM4(al, aLo + aO[ks] + mi * (16 * 64));
#pragma unroll
                for (int nj = 0; nj < 4; nj++) {
                    const uint32_t* bph = bh[nj >> 1] + ((nj & 1) << 1);
                    const uint32_t* bpl = bl[nj >> 1] + ((nj & 1) << 1);
                    MMA16816(acc[mi][nj], ah, bph[0], bph[1]);
                    MMA16816(acc[mi][nj], ah, bpl[0], bpl[1]);
                    MMA16816(acc[mi][nj], al, bph[0], bph[1]);
                }
            }
        }
    }
#undef ISSUE_STAGE

    const int l4 = lid >> 2;
    const int lc = (lid & 3) * 2;
#pragma unroll
    for (int mi = 0; mi < 4; mi++) {
        const int row = m0 + warp_m * 64 + mi * 16 + l4;
#pragma unroll
        for (int nj = 0; nj < 4; nj++) {
            const int col = n0 + warp_n * 32 + nj * 8 + lc;
            const float b0 = bias[col], b1 = bias[col + 1];
            float2 v0 = make_float2(acc[mi][nj][0] + b0, acc[mi][nj][1] + b1);
            float2 v1 = make_float2(acc[mi][nj][2] + b0, acc[mi][nj][3] + b1);
            *(float2*)(C + (size_t)row * N + col)       = v0;
            *(float2*)(C + (size_t)(row + 8) * N + col) = v1;
        }
    }
}

// ---------------------------------------------------------------------------
// Fused window attention: 256 threads, R9 math, halved per-thread tiles.
//   phase1: thread (nt=tid&7, mt=tid>>3): rows nt*7..+6, cols mt*2..+1
//   softmax: 8 warps, warp per row
//   phase2: thread (dp=tid&15, nb=tid>>4): rows nb+16i (i<4), cols 2dp..+1
// ---------------------------------------------------------------------------
#define SCPAD 68

__global__ __launch_bounds__(256)
void window_attn_kernel(const float* __restrict__ qkv,
                        const float* __restrict__ mask,
                        const float* __restrict__ rpb,
                        __nv_bfloat16* __restrict__ aoh,
                        __nv_bfloat16* __restrict__ aol)
{
    const int b = blockIdx.x >> 4;
    const int h = blockIdx.x & 15;
    const int tid = threadIdx.x;
    const int wid = tid >> 5, lid = tid & 31;

    __shared__ float qs[56][36];
    __shared__ float ks[64][36];
    __shared__ float vs[64][36];
    __shared__ float sc[56][SCPAD];

    const size_t base = (size_t)b * NTOK * (3 * CDIM) + h * HDIM;
    for (int idx = tid; idx < NTOK * HDIM; idx += 256) {
        const int n = idx >> 5, d = idx & 31;
        const size_t off = base + (size_t)n * (3 * CDIM) + d;
        qs[n][d] = qkv[off] * QK_SCALE;
        ks[n][d] = qkv[off + CDIM];
        vs[n][d] = qkv[off + 2 * CDIM];
    }
    for (int idx = tid; idx < 15 * HDIM; idx += 256) {
        const int n = NTOK + (idx >> 5), d = idx & 31;
        if (n < 56) qs[n][d] = 0.f;
        ks[n][d] = 0.f;
        vs[n][d] = 0.f;
    }
    __syncthreads();

    // ---- phase1: scores (56x64 padded); k loads broadcast, q conflict-free
    const float* mrow = mask + (size_t)(b & (NWIN - 1)) * NTOK * NTOK;
    {
        const int nt = tid & 7;          // rows nt*7 .. nt*7+6
        const int mt = tid >> 3;         // cols mt*2 .. mt*2+1 (0..62)
        float a[7][2];
#pragma unroll
        for (int i = 0; i < 7; i++) { a[i][0] = 0.f; a[i][1] = 0.f; }

#pragma unroll
        for (int d4 = 0; d4 < 8; d4++) {
            float4 k4[2];
#pragma unroll
            for (int j = 0; j < 2; j++) k4[j] = *(float4*)&ks[mt * 2 + j][d4 * 4];
#pragma unroll
            for (int i = 0; i < 7; i++) {
                float4 q4 = *(float4*)&qs[nt * 7 + i][d4 * 4];
#pragma unroll
                for (int j = 0; j < 2; j++)
                    a[i][j] += q4.x * k4[j].x + q4.y * k4[j].y
                             + q4.z * k4[j].z + q4.w * k4[j].w;
            }
        }
#pragma unroll
        for (int i = 0; i < 7; i++) {
            const int n = nt * 7 + i;
#pragma unroll
            for (int j = 0; j < 2; j++) {
                const int m = mt * 2 + j;
                float v;
                if (n < NTOK && m < NTOK) {
                    const int ridx = (n / 7 - m / 7 + 6) * 13 + (n % 7 - m % 7 + 6);
                    v = a[i][j] + rpb[ridx * NHEAD + h] + mrow[n * NTOK + m];
                } else {
                    v = (n < NTOK) ? -3.0e38f : 0.f;
                }
                sc[n][m] = v;
            }
        }
    }
    __syncthreads();

    // ---- softmax: warp per row over 64 cols (8 warps) ----
    for (int r = wid; r < NTOK; r += 8) {
        float v0 = sc[r][lid];
        float v1 = sc[r][lid + 32];
        float mx = fmaxf(v0, v1);
#pragma unroll
        for (int o = 16; o; o >>= 1) mx = fmaxf(mx, __shfl_xor_sync(~0u, mx, o));
        float e0 = __expf(v0 - mx);
        float e1 = __expf(v1 - mx);
        float s = e0 + e1;
#pragma unroll
        for (int o = 16; o; o >>= 1) s += __shfl_xor_sync(~0u, s, o);
        const float inv = 1.f / s;
        sc[r][lid] = e0 * inv;
        sc[r][lid + 32] = e1 * inv;
    }
    __syncthreads();

    // ---- phase2: out = P @ V; sc reads broadcast, v reads conflict-free
    {
        const int dp = tid & 15;         // d cols 2dp, 2dp+1
        const int nb = tid >> 4;         // rows nb + 16i, i = 0..3
        float ac[4][2];
#pragma unroll
        for (int i = 0; i < 4; i++) { ac[i][0] = 0.f; ac[i][1] = 0.f; }

#pragma unroll
        for (int m4 = 0; m4 < 16; m4++) {
            float2 v2[4];
#pragma unroll
            for (int k = 0; k < 4; k++) v2[k] = *(float2*)&vs[m4 * 4 + k][dp * 2];
#pragma unroll
            for (int i = 0; i < 4; i++) {
                const int n = nb + 16 * i;
                if (n < 56) {            // rows 49..55 are zero-padded, safe
                    float4 s4 = *(float4*)&sc[n][m4 * 4];
                    ac[i][0] += s4.x * v2[0].x + s4.y * v2[1].x
                              + s4.z * v2[2].x + s4.w * v2[3].x;
                    ac[i][1] += s4.x * v2[0].y + s4.y * v2[1].y
                              + s4.z * v2[2].y + s4.w * v2[3].y;
                }
            }
        }
#pragma unroll
        for (int i = 0; i < 4; i++) {
            const int n = nb + 16 * i;
            if (n < NTOK) {
                const size_t o = (size_t)(b * NTOK + n) * CDIM + h * HDIM + dp * 2;
                uint32_t hp, lp;
                cvt_pair(ac[i][0], ac[i][1], hp, lp);
                *(uint32_t*)(aoh + o) = hp;
                *(uint32_t*)(aol + o) = lp;
            }
        }
    }
}

// ---------------------------------------------------------------------------
extern "C" void kernel_launch(void* const* d_in, const int* in_sizes, int n_in,
                              void* d_out, int out_size)
{
    const float* x      = (const float*)d_in[0];
    const float* mask   = (const float*)d_in[1];
    const float* rpb    = (const float*)d_in[2];
    const float* qkv_w  = (const float*)d_in[3];
    const float* qkv_b  = (const float*)d_in[4];
    const float* proj_w = (const float*)d_in[5];
    const float* proj_b = (const float*)d_in[6];
    float* out = (float*)d_out;

    float *qkv_ptr = nullptr;
    __nv_bfloat16 *xh, *xl, *aoh, *aol, *wqh, *wql, *wph, *wpl;
    cudaGetSymbolAddress((void**)&qkv_ptr, g_qkv);
    cudaGetSymbolAddress((void**)&xh,  g_xh);
    cudaGetSymbolAddress((void**)&xl,  g_xl);
    cudaGetSymbolAddress((void**)&aoh, g_aoh);
    cudaGetSymbolAddress((void**)&aol, g_aol);
    cudaGetSymbolAddress((void**)&wqh, g_wqh);
    cudaGetSymbolAddress((void**)&wql, g_wql);
    cudaGetSymbolAddress((void**)&wph, g_wph);
    cudaGetSymbolAddress((void**)&wpl, g_wpl);

    static bool cfg = false;
    if (!cfg) {
        cudaFuncSetAttribute(hmma_gemm, cudaFuncAttributeMaxDynamicSharedMemorySize,
                             SMEM_GEMM);
        cfg = true;
    }

    {
        int n4 = (M_ROWS * CDIM) / 4;
        split_bf16_kernel<<<(n4 + 255) / 256, 256>>>(
            (const float4*)x, (uint2*)xh, (uint2*)xl, n4);
        n4 = (3 * CDIM * CDIM) / 4;
        split_bf16_kernel<<<(n4 + 255) / 256, 256>>>(
            (const float4*)qkv_w, (uint2*)wqh, (uint2*)wql, n4);
        n4 = (CDIM * CDIM) / 4;
        split_bf16_kernel<<<(n4 + 255) / 256, 256>>>(
            (const float4*)proj_w, (uint2*)wph, (uint2*)wpl, n4);
    }

    hmma_gemm<<<dim3((3 * CDIM) / 128, M_ROWS / 128), 256, SMEM_GEMM>>>(
        xh, xl, wqh, wql, qkv_b, qkv_ptr, 3 * CDIM, CDIM);

    window_attn_kernel<<<B_TOT * NHEAD, 256>>>(qkv_ptr, mask, rpb, aoh, aol);

    hmma_gemm<<<dim3(CDIM / 128, M_ROWS / 128), 256, SMEM_GEMM>>>(
        aoh, aol, wph, wpl, proj_b, out, CDIM, CDIM);
}

// round 12
// speedup vs baseline: 1.1477x; 1.0686x over previous
#include <cuda_runtime.h>
#include <cuda_bf16.h>
#include <cstdint>

// ---------------------------------------------------------------------------
// Swin window attention: B_=2048, N=49, H=16, D=32, C=512, nW=64, fp32.
// Split-bf16 HMMA GEMM (R9 winner) + HMMA-based fused attention (split-bf16
// QK^T and P@V on tensor cores, conflict-free rotated smem layouts).
// ---------------------------------------------------------------------------
#define B_TOT   2048
#define NTOK    49
#define NHEAD   16
#define HDIM    32
#define CDIM    512
#define NWIN    64
#define QK_SCALE 0.17677669529663687f
#define M_ROWS  (B_TOT * NTOK)          // 100352 = 784 * 128

__device__ float          g_qkv[(size_t)M_ROWS * 3 * CDIM];
__device__ __nv_bfloat16  g_xh [(size_t)M_ROWS * CDIM];
__device__ __nv_bfloat16  g_xl [(size_t)M_ROWS * CDIM];
__device__ __nv_bfloat16  g_aoh[(size_t)M_ROWS * CDIM];
__device__ __nv_bfloat16  g_aol[(size_t)M_ROWS * CDIM];
__device__ __nv_bfloat16  g_wqh[3 * CDIM * CDIM];
__device__ __nv_bfloat16  g_wql[3 * CDIM * CDIM];
__device__ __nv_bfloat16  g_wph[CDIM * CDIM];
__device__ __nv_bfloat16  g_wpl[CDIM * CDIM];

// ---------------------------------------------------------------------------
__device__ __forceinline__ uint32_t smem_u32(const void* p) {
    uint32_t a;
    asm("{ .reg .u64 t; cvta.to.shared.u64 t, %1; cvt.u32.u64 %0, t; }"
        : "=r"(a) : "l"(p));
    return a;
}

__device__ __forceinline__ void cvt_pair(float x, float y, uint32_t& hp, uint32_t& lp) {
    unsigned short h0 = __bfloat16_as_ushort(__float2bfloat16_rn(x));
    unsigned short h1 = __bfloat16_as_ushort(__float2bfloat16_rn(y));
    hp = (uint32_t)h0 | ((uint32_t)h1 << 16);
    float l0 = x - __uint_as_float((uint32_t)h0 << 16);
    float l1 = y - __uint_as_float((uint32_t)h1 << 16);
    asm("cvt.rn.bf16x2.f32 %0, %1, %2;" : "=r"(lp) : "f"(l1), "f"(l0));
}

#define LDSM4(r, addr) \
    asm volatile("ldmatrix.sync.aligned.m8n8.x4.shared.b16 {%0,%1,%2,%3}, [%4];" \
        : "=r"((r)[0]), "=r"((r)[1]), "=r"((r)[2]), "=r"((r)[3]) : "r"(addr))

#define MMA16816(d, a, b0, b1) \
    asm volatile("mma.sync.aligned.m16n8k16.row.col.f32.bf16.bf16.f32 " \
        "{%0,%1,%2,%3}, {%4,%5,%6,%7}, {%8,%9}, {%0,%1,%2,%3};" \
        : "+f"((d)[0]), "+f"((d)[1]), "+f"((d)[2]), "+f"((d)[3]) \
        : "r"((a)[0]), "r"((a)[1]), "r"((a)[2]), "r"((a)[3]), "r"(b0), "r"(b1))

#define CP16(saddr, gaddr) \
    asm volatile("cp.async.cg.shared.global [%0], [%1], 16;" :: "r"(saddr), "l"(gaddr))
#define CP_COMMIT() asm volatile("cp.async.commit_group;" ::: "memory")
#define CP_WAIT(n)  asm volatile("cp.async.wait_group %0;" :: "n"(n) : "memory")

// ---------------------------------------------------------------------------
__global__ void split_bf16_kernel(const float4* __restrict__ src,
                                  uint2* __restrict__ dh, uint2* __restrict__ dl,
                                  int n4)
{
    int i = blockIdx.x * blockDim.x + threadIdx.x;
    if (i < n4) {
        float4 v = src[i];
        uint32_t h0, l0, h1, l1;
        cvt_pair(v.x, v.y, h0, l0);
        cvt_pair(v.z, v.w, h1, l1);
        dh[i] = make_uint2(h0, h1);
        dl[i] = make_uint2(l0, l1);
    }
}

// ---------------------------------------------------------------------------
// HMMA split-bf16 GEMM (R9 winner, unchanged).
// ---------------------------------------------------------------------------
#define TILE_SZ   8192
#define STAGE_SZ  32768
#define SMEM_GEMM 98304

__global__ __launch_bounds__(256, 2)
void hmma_gemm(const __nv_bfloat16* __restrict__ Ah, const __nv_bfloat16* __restrict__ Al,
               const __nv_bfloat16* __restrict__ Bh, const __nv_bfloat16* __restrict__ Bl,
               const float* __restrict__ bias, float* __restrict__ C,
               int N, int K)
{
    extern __shared__ char sm[];
    const uint32_t sb = smem_u32(sm);

    const int tid = threadIdx.x;
    const int wid = tid >> 5, lid = tid & 31;
    const int warp_m = wid & 1;
    const int warp_n = wid >> 1;
    const int m0 = blockIdx.y * 128;
    const int n0 = blockIdx.x * 128;

    const __nv_bfloat16* gbase[4] = {
        Ah + (size_t)m0 * K, Al + (size_t)m0 * K,
        Bh + (size_t)n0 * K, Bl + (size_t)n0 * K };

    const uint32_t aRowL = (uint32_t)(warp_m * 64 + (lid & 15));
    const uint32_t ac    = (uint32_t)(lid >> 4);
    const uint32_t arot  = (aRowL >> 1) & 3;
    const uint32_t aO[2] = { aRowL * 64 + ((ac + arot) & 3) * 16,
                             aRowL * 64 + ((ac + 2 + arot) & 3) * 16 };
    const uint32_t bRowL = (uint32_t)(warp_n * 32 + ((lid >> 4) << 3) + (lid & 7));
    const uint32_t bc    = (uint32_t)((lid >> 3) & 1);
    const uint32_t brot  = (bRowL >> 1) & 3;
    const uint32_t bO[2] = { bRowL * 64 + ((bc + brot) & 3) * 16,
                             bRowL * 64 + ((bc + 2 + brot) & 3) * 16 };

    float acc[4][4][4];
#pragma unroll
    for (int i = 0; i < 4; i++)
#pragma unroll
        for (int j = 0; j < 4; j++)
#pragma unroll
            for (int e = 0; e < 4; e++) acc[i][j][e] = 0.f;

    const int iters = K >> 5;

#define ISSUE_STAGE(it) do {                                                  \
        const int kblk = (it) * 32;                                           \
        const uint32_t stb = sb + ((it) % 3) * STAGE_SZ;                      \
        _Pragma("unroll")                                                     \
        for (int s = 0; s < 8; s++) {                                         \
            const int id   = tid + s * 256;                                   \
            const int tile = id >> 9;                                         \
            const int row  = (id >> 2) & 127;                                 \
            const int c    = id & 3;                                          \
            const int cc   = (c + ((row >> 1) & 3)) & 3;                      \
            CP16(stb + tile * TILE_SZ + row * 64 + cc * 16,                   \
                 gbase[tile] + (size_t)row * K + kblk + c * 8);               \
        }                                                                     \
    } while (0)

    ISSUE_STAGE(0); CP_COMMIT();
    ISSUE_STAGE(1); CP_COMMIT();

    for (int i = 0; i < iters; i++) {
        if (i + 1 < iters) CP_WAIT(1); else CP_WAIT(0);
        __syncthreads();
        if (i + 2 < iters) { ISSUE_STAGE(i + 2); CP_COMMIT(); }

        const uint32_t st  = sb + (i % 3) * STAGE_SZ;
        const uint32_t aHi = st;
        const uint32_t aLo = st + TILE_SZ;
        const uint32_t bHi = st + 2 * TILE_SZ;
        const uint32_t bLo = st + 3 * TILE_SZ;

#pragma unroll
        for (int ks = 0; ks < 2; ks++) {
            uint32_t bh[2][4], bl[2][4];
            LDSM4(bh[0], bHi + bO[ks]);
            LDSM4(bh[1], bHi + bO[ks] + 16 * 64);
            LDSM4(bl[0], bLo + bO[ks]);
            LDSM4(bl[1], bLo + bO[ks] + 16 * 64);
#pragma unroll
            for (int mi = 0; mi < 4; mi++) {
                uint32_t ah[4], al[4];
                LDSM4(ah, aHi + aO[ks] + mi * (16 * 64));
                LDSM4(al, aLo + aO[ks] + mi * (16 * 64));
#pragma unroll
                for (int nj = 0; nj < 4; nj++) {
                    const uint32_t* bph = bh[nj >> 1] + ((nj & 1) << 1);
                    const uint32_t* bpl = bl[nj >> 1] + ((nj & 1) << 1);
                    MMA16816(acc[mi][nj], ah, bph[0], bph[1]);
                    MMA16816(acc[mi][nj], ah, bpl[0], bpl[1]);
                    MMA16816(acc[mi][nj], al, bph[0], bph[1]);
                }
            }
        }
    }
#undef ISSUE_STAGE

    const int l4 = lid >> 2;
    const int lc = (lid & 3) * 2;
#pragma unroll
    for (int mi = 0; mi < 4; mi++) {
        const int row = m0 + warp_m * 64 + mi * 16 + l4;
#pragma unroll
        for (int nj = 0; nj < 4; nj++) {
            const int col = n0 + warp_n * 32 + nj * 8 + lc;
            const float b0 = bias[col], b1 = bias[col + 1];
            float2 v0 = make_float2(acc[mi][nj][0] + b0, acc[mi][nj][1] + b1);
            float2 v1 = make_float2(acc[mi][nj][2] + b0, acc[mi][nj][3] + b1);
            *(float2*)(C + (size_t)row * N + col)       = v0;
            *(float2*)(C + (size_t)(row + 8) * N + col) = v1;
        }
    }
}

// ---------------------------------------------------------------------------
// HMMA fused window attention. One CTA per (b,h), 256 threads / 8 warps.
// SMEM map (42 KB static):
//   [0,4K)qh [4K,8K)ql [8K,12K)kh [12K,16K)kl   (64 rows x 64B, 4-chunk rot)
//     -> reused after phase1 as [0,8K)ph [8K,16K)pl (64 rows x 128B, 8-chunk)
//   [16K,20K)vth [20K,24K)vtl   (32 d-rows x 128B(64 m), 8-chunk rot)
//   [24K, +17408) sc fp32 [64][68]
// ---------------------------------------------------------------------------
__global__ __launch_bounds__(256)
void window_attn_hmma(const float* __restrict__ qkv,
                      const float* __restrict__ mask,
                      const float* __restrict__ rpb,
                      __nv_bfloat16* __restrict__ aoh,
                      __nv_bfloat16* __restrict__ aol)
{
    __shared__ __align__(16) char smA[41984];
    const uint32_t sb = smem_u32(smA);
    float* sc = (float*)(smA + 24576);

    const int b = blockIdx.x >> 4;
    const int h = blockIdx.x & 15;
    const int tid = threadIdx.x;
    const int wid = tid >> 5, lid = tid & 31;

    const size_t base = (size_t)b * NTOK * (3 * CDIM) + h * HDIM;

    // --- load+convert Q (scaled), K: 64 rows x 32 bf16, rows 49..63 zero ---
    for (int idx = tid; idx < 64 * 16; idx += 256) {
        const int n = idx >> 4;
        const int p = idx & 15;                 // fp32 pair (cols 2p, 2p+1)
        float q0 = 0.f, q1 = 0.f, k0 = 0.f, k1 = 0.f;
        if (n < NTOK) {
            const float* src = qkv + base + (size_t)n * (3 * CDIM) + 2 * p;
            q0 = src[0] * QK_SCALE; q1 = src[1] * QK_SCALE;
            k0 = src[CDIM];         k1 = src[CDIM + 1];
        }
        const uint32_t off = n * 64 + (((p >> 2) + ((n >> 1) & 3)) & 3) * 16
                           + (p & 3) * 4;
        uint32_t hp, lp;
        cvt_pair(q0, q1, hp, lp);
        *(uint32_t*)(smA + off)         = hp;
        *(uint32_t*)(smA + 4096 + off)  = lp;
        cvt_pair(k0, k1, hp, lp);
        *(uint32_t*)(smA + 8192 + off)  = hp;
        *(uint32_t*)(smA + 12288 + off) = lp;
    }
    // --- load+convert V transposed: vt[d][m], m-pairs packed ---
    for (int idx = tid; idx < 32 * 32; idx += 256) {
        const int d  = idx & 31;
        const int m2 = idx >> 5;                // m pair (2m2, 2m2+1)
        float v0 = 0.f, v1 = 0.f;
        const float* src = qkv + base + 2 * CDIM + d;
        if (2 * m2 < NTOK)     v0 = src[(size_t)(2 * m2) * (3 * CDIM)];
        if (2 * m2 + 1 < NTOK) v1 = src[(size_t)(2 * m2 + 1) * (3 * CDIM)];
        uint32_t hp, lp;
        cvt_pair(v0, v1, hp, lp);
        const uint32_t off = d * 128 + (((m2 >> 2) + d) & 7) * 16 + (m2 & 3) * 4;
        *(uint32_t*)(smA + 16384 + off) = hp;
        *(uint32_t*)(smA + 20480 + off) = lp;
    }
    __syncthreads();

    // --- phase1: S = Q @ K^T  (M=64, N=64, K=32), warp tile 32x16 ---
    {
        const int wm = wid & 1;
        const int wn = wid >> 1;
        float acc[2][2][4];
#pragma unroll
        for (int i = 0; i < 2; i++)
#pragma unroll
            for (int j = 0; j < 2; j++)
#pragma unroll
                for (int e = 0; e < 4; e++) acc[i][j][e] = 0.f;

        const int brow  = wn * 16 + ((lid >> 4) << 3) + (lid & 7);
        const int bcsel = (lid >> 3) & 1;
        const int acsel = lid >> 4;
#pragma unroll
        for (int ks = 0; ks < 2; ks++) {
            uint32_t bh[4], bl[4];
            const uint32_t baddr = sb + 8192 + brow * 64
                + (((2 * ks + bcsel) + ((brow >> 1) & 3)) & 3) * 16;
            LDSM4(bh, baddr);
            LDSM4(bl, baddr + 4096);
#pragma unroll
            for (int mi = 0; mi < 2; mi++) {
                const int arow = wm * 32 + mi * 16 + (lid & 15);
                const uint32_t aaddr = sb + arow * 64
                    + (((2 * ks + acsel) + ((arow >> 1) & 3)) & 3) * 16;
                uint32_t ah[4], al[4];
                LDSM4(ah, aaddr);
                LDSM4(al, aaddr + 4096);
#pragma unroll
                for (int nj = 0; nj < 2; nj++) {
                    MMA16816(acc[mi][nj], ah, bh[nj * 2], bh[nj * 2 + 1]);
                    MMA16816(acc[mi][nj], ah, bl[nj * 2], bl[nj * 2 + 1]);
                    MMA16816(acc[mi][nj], al, bh[nj * 2], bh[nj * 2 + 1]);
                }
            }
        }

        // epilogue: + rpb + mask -> sc (pad rows -> 0, pad cols -> -inf)
        const float* mrow = mask + (size_t)(b & (NWIN - 1)) * NTOK * NTOK;
        const int r4 = lid >> 2, c2 = (lid & 3) * 2;
#pragma unroll
        for (int mi = 0; mi < 2; mi++)
#pragma unroll
            for (int nj = 0; nj < 2; nj++)
#pragma unroll
                for (int e = 0; e < 4; e++) {
                    const int n = wm * 32 + mi * 16 + r4 + (e >> 1) * 8;
                    const int m = wn * 16 + nj * 8 + c2 + (e & 1);
                    float v;
                    if (n >= NTOK)      v = 0.f;
                    else if (m >= NTOK) v = -3.0e38f;
                    else {
                        const int ridx = (n / 7 - m / 7 + 6) * 13
                                       + (n % 7 - m % 7 + 6);
                        v = acc[mi][nj][e] + rpb[ridx * NHEAD + h]
                          + mrow[n * NTOK + m];
                    }
                    sc[n * 68 + m] = v;
                }
    }
    __syncthreads();

    // --- softmax: warp per row over 64 cols (8 warps) ---
    for (int r = wid; r < NTOK; r += 8) {
        float v0 = sc[r * 68 + lid];
        float v1 = sc[r * 68 + lid + 32];
        float mx = fmaxf(v0, v1);
#pragma unroll
        for (int o = 16; o; o >>= 1) mx = fmaxf(mx, __shfl_xor_sync(~0u, mx, o));
        float e0 = __expf(v0 - mx);
        float e1 = __expf(v1 - mx);
        float s = e0 + e1;
#pragma unroll
        for (int o = 16; o; o >>= 1) s += __shfl_xor_sync(~0u, s, o);
        const float inv = 1.f / s;
        sc[r * 68 + lid]      = e0 * inv;
        sc[r * 68 + lid + 32] = e1 * inv;
    }
    __syncthreads();

    // --- convert P -> split bf16 (64 rows x 64 bf16 = 128B rows, 8-chunk rot)
    //     overwrites q/k region (free after phase1)
    for (int idx = tid; idx < 64 * 8; idx += 256) {
        const int n = idx >> 3;
        const int c = idx & 7;
        const float* s = sc + n * 68 + c * 8;
        uint32_t h0, l0, h1, l1, h2, l2, h3, l3;
        cvt_pair(s[0], s[1], h0, l0);
        cvt_pair(s[2], s[3], h1, l1);
        cvt_pair(s[4], s[5], h2, l2);
        cvt_pair(s[6], s[7], h3, l3);
        const uint32_t off = n * 128 + ((c + n) & 7) * 16;
        *(uint4*)(smA + off)        = make_uint4(h0, h1, h2, h3);
        *(uint4*)(smA + 8192 + off) = make_uint4(l0, l1, l2, l3);
    }
    __syncthreads();

    // --- phase2: O = P @ V  (M=64, N=32, K=64), warp tile 16x16 ---
    {
        const int wm = wid & 3;
        const int wn = wid >> 2;
        float acc[2][4];
#pragma unroll
        for (int j = 0; j < 2; j++)
#pragma unroll
            for (int e = 0; e < 4; e++) acc[j][e] = 0.f;

        const int arow  = wm * 16 + (lid & 15);
        const int acsel = lid >> 4;
        const int brow  = wn * 16 + ((lid >> 4) << 3) + (lid & 7);
        const int bcsel = (lid >> 3) & 1;
#pragma unroll
        for (int ks = 0; ks < 4; ks++) {
            uint32_t ah[4], al[4], bh[4], bl[4];
            const uint32_t aaddr = sb + arow * 128
                + (((2 * ks + acsel) + arow) & 7) * 16;
            LDSM4(ah, aaddr);
            LDSM4(al, aaddr + 8192);
            const uint32_t baddr = sb + 16384 + brow * 128
                + (((2 * ks + bcsel) + brow) & 7) * 16;
            LDSM4(bh, baddr);
            LDSM4(bl, baddr + 4096);
#pragma unroll
            for (int nj = 0; nj < 2; nj++) {
                MMA16816(acc[nj], ah, bh[nj * 2], bh[nj * 2 + 1]);
                MMA16816(acc[nj], ah, bl[nj * 2], bl[nj * 2 + 1]);
                MMA16816(acc[nj], al, bh[nj * 2], bh[nj * 2 + 1]);
            }
        }

        // epilogue: write split-bf16 output (rows n < 49)
        const int r4 = lid >> 2, c2 = (lid & 3) * 2;
#pragma unroll
        for (int nj = 0; nj < 2; nj++)
#pragma unroll
            for (int half = 0; half < 2; half++) {
                const int n = wm * 16 + r4 + half * 8;
                if (n < NTOK) {
                    const int d = wn * 16 + nj * 8 + c2;
                    const size_t o = (size_t)(b * NTOK + n) * CDIM
                                   + h * HDIM + d;
                    uint32_t hp, lp;
                    cvt_pair(acc[nj][half * 2], acc[nj][half * 2 + 1], hp, lp);
                    *(uint32_t*)(aoh + o) = hp;
                    *(uint32_t*)(aol + o) = lp;
                }
            }
    }
}

// ---------------------------------------------------------------------------
extern "C" void kernel_launch(void* const* d_in, const int* in_sizes, int n_in,
                              void* d_out, int out_size)
{
    const float* x      = (const float*)d_in[0];
    const float* mask   = (const float*)d_in[1];
    const float* rpb    = (const float*)d_in[2];
    const float* qkv_w  = (const float*)d_in[3];
    const float* qkv_b  = (const float*)d_in[4];
    const float* proj_w = (const float*)d_in[5];
    const float* proj_b = (const float*)d_in[6];
    float* out = (float*)d_out;

    float *qkv_ptr = nullptr;
    __nv_bfloat16 *xh, *xl, *aoh, *aol, *wqh, *wql, *wph, *wpl;
    cudaGetSymbolAddress((void**)&qkv_ptr, g_qkv);
    cudaGetSymbolAddress((void**)&xh,  g_xh);
    cudaGetSymbolAddress((void**)&xl,  g_xl);
    cudaGetSymbolAddress((void**)&aoh, g_aoh);
    cudaGetSymbolAddress((void**)&aol, g_aol);
    cudaGetSymbolAddress((void**)&wqh, g_wqh);
    cudaGetSymbolAddress((void**)&wql, g_wql);
    cudaGetSymbolAddress((void**)&wph, g_wph);
    cudaGetSymbolAddress((void**)&wpl, g_wpl);

    static bool cfg = false;
    if (!cfg) {
        cudaFuncSetAttribute(hmma_gemm, cudaFuncAttributeMaxDynamicSharedMemorySize,
                             SMEM_GEMM);
        cfg = true;
    }

    {
        int n4 = (M_ROWS * CDIM) / 4;
        split_bf16_kernel<<<(n4 + 255) / 256, 256>>>(
            (const float4*)x, (uint2*)xh, (uint2*)xl, n4);
        n4 = (3 * CDIM * CDIM) / 4;
        split_bf16_kernel<<<(n4 + 255) / 256, 256>>>(
            (const float4*)qkv_w, (uint2*)wqh, (uint2*)wql, n4);
        n4 = (CDIM * CDIM) / 4;
        split_bf16_kernel<<<(n4 + 255) / 256, 256>>>(
            (const float4*)proj_w, (uint2*)wph, (uint2*)wpl, n4);
    }

    hmma_gemm<<<dim3((3 * CDIM) / 128, M_ROWS / 128), 256, SMEM_GEMM>>>(
        xh, xl, wqh, wql, qkv_b, qkv_ptr, 3 * CDIM, CDIM);

    window_attn_hmma<<<B_TOT * NHEAD, 256>>>(qkv_ptr, mask, rpb, aoh, aol);

    hmma_gemm<<<dim3(CDIM / 128, M_ROWS / 128), 256, SMEM_GEMM>>>(
        aoh, aol, wph, wpl, proj_b, out, CDIM, CDIM);
}

// round 13
// speedup vs baseline: 1.2202x; 1.0632x over previous
#include <cuda_runtime.h>
#include <cuda_bf16.h>
#include <cstdint>

// ---------------------------------------------------------------------------
// Swin window attention: B_=2048, N=49, H=16, D=32, C=512, nW=64, fp32.
// Split-bf16 HMMA GEMM (R9 winner) + HMMA fused attention (R12 winner) with
// precomputed rpb+mask bias table (kills per-window epilogue index math).
// ---------------------------------------------------------------------------
#define B_TOT   2048
#define NTOK    49
#define NHEAD   16
#define HDIM    32
#define CDIM    512
#define NWIN    64
#define QK_SCALE 0.17677669529663687f
#define M_ROWS  (B_TOT * NTOK)          // 100352 = 784 * 128
#define BT_ROW  52                      // padded bias row (float2-aligned)

__device__ float          g_qkv[(size_t)M_ROWS * 3 * CDIM];
__device__ float          g_bias[NWIN * NHEAD * NTOK * BT_ROW];
__device__ __nv_bfloat16  g_xh [(size_t)M_ROWS * CDIM];
__device__ __nv_bfloat16  g_xl [(size_t)M_ROWS * CDIM];
__device__ __nv_bfloat16  g_aoh[(size_t)M_ROWS * CDIM];
__device__ __nv_bfloat16  g_aol[(size_t)M_ROWS * CDIM];
__device__ __nv_bfloat16  g_wqh[3 * CDIM * CDIM];
__device__ __nv_bfloat16  g_wql[3 * CDIM * CDIM];
__device__ __nv_bfloat16  g_wph[CDIM * CDIM];
__device__ __nv_bfloat16  g_wpl[CDIM * CDIM];

// ---------------------------------------------------------------------------
__device__ __forceinline__ uint32_t smem_u32(const void* p) {
    uint32_t a;
    asm("{ .reg .u64 t; cvta.to.shared.u64 t, %1; cvt.u32.u64 %0, t; }"
        : "=r"(a) : "l"(p));
    return a;
}

__device__ __forceinline__ void cvt_pair(float x, float y, uint32_t& hp, uint32_t& lp) {
    unsigned short h0 = __bfloat16_as_ushort(__float2bfloat16_rn(x));
    unsigned short h1 = __bfloat16_as_ushort(__float2bfloat16_rn(y));
    hp = (uint32_t)h0 | ((uint32_t)h1 << 16);
    float l0 = x - __uint_as_float((uint32_t)h0 << 16);
    float l1 = y - __uint_as_float((uint32_t)h1 << 16);
    asm("cvt.rn.bf16x2.f32 %0, %1, %2;" : "=r"(lp) : "f"(l1), "f"(l0));
}

#define LDSM4(r, addr) \
    asm volatile("ldmatrix.sync.aligned.m8n8.x4.shared.b16 {%0,%1,%2,%3}, [%4];" \
        : "=r"((r)[0]), "=r"((r)[1]), "=r"((r)[2]), "=r"((r)[3]) : "r"(addr))

#define MMA16816(d, a, b0, b1) \
    asm volatile("mma.sync.aligned.m16n8k16.row.col.f32.bf16.bf16.f32 " \
        "{%0,%1,%2,%3}, {%4,%5,%6,%7}, {%8,%9}, {%0,%1,%2,%3};" \
        : "+f"((d)[0]), "+f"((d)[1]), "+f"((d)[2]), "+f"((d)[3]) \
        : "r"((a)[0]), "r"((a)[1]), "r"((a)[2]), "r"((a)[3]), "r"(b0), "r"(b1))

#define CP16(saddr, gaddr) \
    asm volatile("cp.async.cg.shared.global [%0], [%1], 16;" :: "r"(saddr), "l"(gaddr))
#define CP_COMMIT() asm volatile("cp.async.commit_group;" ::: "memory")
#define CP_WAIT(n)  asm volatile("cp.async.wait_group %0;" :: "n"(n) : "memory")

// ---------------------------------------------------------------------------
__global__ void split_bf16_kernel(const float4* __restrict__ src,
                                  uint2* __restrict__ dh, uint2* __restrict__ dl,
                                  int n4)
{
    int i = blockIdx.x * blockDim.x + threadIdx.x;
    if (i < n4) {
        float4 v = src[i];
        uint32_t h0, l0, h1, l1;
        cvt_pair(v.x, v.y, h0, l0);
        cvt_pair(v.z, v.w, h1, l1);
        dh[i] = make_uint2(h0, h1);
        dl[i] = make_uint2(l0, l1);
    }
}

// bias table: bt[bw][h][n][m_pad52] = rpb[ridx(n,m)*16+h] + mask[bw][n][m]
__global__ void build_bias_kernel(const float* __restrict__ mask,
                                  const float* __restrict__ rpb,
                                  float* __restrict__ bt)
{
    const int idx = blockIdx.x * 256 + threadIdx.x;
    const int total = NWIN * NHEAD * NTOK * BT_ROW;
    if (idx >= total) return;
    const int m  = idx % BT_ROW;
    const int n  = (idx / BT_ROW) % NTOK;
    const int h  = (idx / (BT_ROW * NTOK)) % NHEAD;
    const int bw = idx / (BT_ROW * NTOK * NHEAD);
    float v = 0.f;
    if (m < NTOK) {
        const int ridx = (n / 7 - m / 7 + 6) * 13 + (n % 7 - m % 7 + 6);
        v = rpb[ridx * NHEAD + h] + mask[(bw * NTOK + n) * NTOK + m];
    }
    bt[idx] = v;
}

// ---------------------------------------------------------------------------
// HMMA split-bf16 GEMM (R9 winner, unchanged).
// ---------------------------------------------------------------------------
#define TILE_SZ   8192
#define STAGE_SZ  32768
#define SMEM_GEMM 98304

__global__ __launch_bounds__(256, 2)
void hmma_gemm(const __nv_bfloat16* __restrict__ Ah, const __nv_bfloat16* __restrict__ Al,
               const __nv_bfloat16* __restrict__ Bh, const __nv_bfloat16* __restrict__ Bl,
               const float* __restrict__ bias, float* __restrict__ C,
               int N, int K)
{
    extern __shared__ char sm[];
    const uint32_t sb = smem_u32(sm);

    const int tid = threadIdx.x;
    const int wid = tid >> 5, lid = tid & 31;
    const int warp_m = wid & 1;
    const int warp_n = wid >> 1;
    const int m0 = blockIdx.y * 128;
    const int n0 = blockIdx.x * 128;

    const __nv_bfloat16* gbase[4] = {
        Ah + (size_t)m0 * K, Al + (size_t)m0 * K,
        Bh + (size_t)n0 * K, Bl + (size_t)n0 * K };

    const uint32_t aRowL = (uint32_t)(warp_m * 64 + (lid & 15));
    const uint32_t ac    = (uint32_t)(lid >> 4);
    const uint32_t arot  = (aRowL >> 1) & 3;
    const uint32_t aO[2] = { aRowL * 64 + ((ac + arot) & 3) * 16,
                             aRowL * 64 + ((ac + 2 + arot) & 3) * 16 };
    const uint32_t bRowL = (uint32_t)(warp_n * 32 + ((lid >> 4) << 3) + (lid & 7));
    const uint32_t bc    = (uint32_t)((lid >> 3) & 1);
    const uint32_t brot  = (bRowL >> 1) & 3;
    const uint32_t bO[2] = { bRowL * 64 + ((bc + brot) & 3) * 16,
                             bRowL * 64 + ((bc + 2 + brot) & 3) * 16 };

    float acc[4][4][4];
#pragma unroll
    for (int i = 0; i < 4; i++)
#pragma unroll
        for (int j = 0; j < 4; j++)
#pragma unroll
            for (int e = 0; e < 4; e++) acc[i][j][e] = 0.f;

    const int iters = K >> 5;

#define ISSUE_STAGE(it) do {                                                  \
        const int kblk = (it) * 32;                                           \
        const uint32_t stb = sb + ((it) % 3) * STAGE_SZ;                      \
        _Pragma("unroll")                                                     \
        for (int s = 0; s < 8; s++) {                                         \
            const int id   = tid + s * 256;                                   \
            const int tile = id >> 9;                                         \
            const int row  = (id >> 2) & 127;                                 \
            const int c    = id & 3;                                          \
            const int cc   = (c + ((row >> 1) & 3)) & 3;                      \
            CP16(stb + tile * TILE_SZ + row * 64 + cc * 16,                   \
                 gbase[tile] + (size_t)row * K + kblk + c * 8);               \
        }                                                                     \
    } while (0)

    ISSUE_STAGE(0); CP_COMMIT();
    ISSUE_STAGE(1); CP_COMMIT();

    for (int i = 0; i < iters; i++) {
        if (i + 1 < iters) CP_WAIT(1); else CP_WAIT(0);
        __syncthreads();
        if (i + 2 < iters) { ISSUE_STAGE(i + 2); CP_COMMIT(); }

        const uint32_t st  = sb + (i % 3) * STAGE_SZ;
        const uint32_t aHi = st;
        const uint32_t aLo = st + TILE_SZ;
        const uint32_t bHi = st + 2 * TILE_SZ;
        const uint32_t bLo = st + 3 * TILE_SZ;

#pragma unroll
        for (int ks = 0; ks < 2; ks++) {
            uint32_t bh[2][4], bl[2][4];
            LDSM4(bh[0], bHi + bO[ks]);
            LDSM4(bh[1], bHi + bO[ks] + 16 * 64);
            LDSM4(bl[0], bLo + bO[ks]);
            LDSM4(bl[1], bLo + bO[ks] + 16 * 64);
#pragma unroll
            for (int mi = 0; mi < 4; mi++) {
                uint32_t ah[4], al[4];
                LDSM4(ah, aHi + aO[ks] + mi * (16 * 64));
                LDSM4(al, aLo + aO[ks] + mi * (16 * 64));
#pragma unroll
                for (int nj = 0; nj < 4; nj++) {
                    const uint32_t* bph = bh[nj >> 1] + ((nj & 1) << 1);
                    const uint32_t* bpl = bl[nj >> 1] + ((nj & 1) << 1);
                    MMA16816(acc[mi][nj], ah, bph[0], bph[1]);
                    MMA16816(acc[mi][nj], ah, bpl[0], bpl[1]);
                    MMA16816(acc[mi][nj], al, bph[0], bph[1]);
                }
            }
        }
    }
#undef ISSUE_STAGE

    const int l4 = lid >> 2;
    const int lc = (lid & 3) * 2;
#pragma unroll
    for (int mi = 0; mi < 4; mi++) {
        const int row = m0 + warp_m * 64 + mi * 16 + l4;
#pragma unroll
        for (int nj = 0; nj < 4; nj++) {
            const int col = n0 + warp_n * 32 + nj * 8 + lc;
            const float b0 = bias[col], b1 = bias[col + 1];
            float2 v0 = make_float2(acc[mi][nj][0] + b0, acc[mi][nj][1] + b1);
            float2 v1 = make_float2(acc[mi][nj][2] + b0, acc[mi][nj][3] + b1);
            *(float2*)(C + (size_t)row * N + col)       = v0;
            *(float2*)(C + (size_t)(row + 8) * N + col) = v1;
        }
    }
}

// ---------------------------------------------------------------------------
// HMMA fused window attention (R12 structure) with precomputed bias table.
// ---------------------------------------------------------------------------
__global__ __launch_bounds__(256)
void window_attn_hmma(const float* __restrict__ qkv,
                      const float* __restrict__ bias_tab,
                      __nv_bfloat16* __restrict__ aoh,
                      __nv_bfloat16* __restrict__ aol)
{
    __shared__ __align__(16) char smA[41984];
    const uint32_t sb = smem_u32(smA);
    float* sc = (float*)(smA + 24576);

    const int b = blockIdx.x >> 4;
    const int h = blockIdx.x & 15;
    const int tid = threadIdx.x;
    const int wid = tid >> 5, lid = tid & 31;

    const size_t base = (size_t)b * NTOK * (3 * CDIM) + h * HDIM;

    // --- load+convert Q (scaled), K ---
    for (int idx = tid; idx < 64 * 16; idx += 256) {
        const int n = idx >> 4;
        const int p = idx & 15;
        float q0 = 0.f, q1 = 0.f, k0 = 0.f, k1 = 0.f;
        if (n < NTOK) {
            const float* src = qkv + base + (size_t)n * (3 * CDIM) + 2 * p;
            q0 = src[0] * QK_SCALE; q1 = src[1] * QK_SCALE;
            k0 = src[CDIM];         k1 = src[CDIM + 1];
        }
        const uint32_t off = n * 64 + (((p >> 2) + ((n >> 1) & 3)) & 3) * 16
                           + (p & 3) * 4;
        uint32_t hp, lp;
        cvt_pair(q0, q1, hp, lp);
        *(uint32_t*)(smA + off)         = hp;
        *(uint32_t*)(smA + 4096 + off)  = lp;
        cvt_pair(k0, k1, hp, lp);
        *(uint32_t*)(smA + 8192 + off)  = hp;
        *(uint32_t*)(smA + 12288 + off) = lp;
    }
    // --- load+convert V transposed ---
    for (int idx = tid; idx < 32 * 32; idx += 256) {
        const int d  = idx & 31;
        const int m2 = idx >> 5;
        float v0 = 0.f, v1 = 0.f;
        const float* src = qkv + base + 2 * CDIM + d;
        if (2 * m2 < NTOK)     v0 = src[(size_t)(2 * m2) * (3 * CDIM)];
        if (2 * m2 + 1 < NTOK) v1 = src[(size_t)(2 * m2 + 1) * (3 * CDIM)];
        uint32_t hp, lp;
        cvt_pair(v0, v1, hp, lp);
        const uint32_t off = d * 128 + (((m2 >> 2) + d) & 7) * 16 + (m2 & 3) * 4;
        *(uint32_t*)(smA + 16384 + off) = hp;
        *(uint32_t*)(smA + 20480 + off) = lp;
    }
    __syncthreads();

    // --- phase1: S = Q @ K^T  (M=64, N=64, K=32), warp tile 32x16 ---
    {
        const int wm = wid & 1;
        const int wn = wid >> 1;
        float acc[2][2][4];
#pragma unroll
        for (int i = 0; i < 2; i++)
#pragma unroll
            for (int j = 0; j < 2; j++)
#pragma unroll
                for (int e = 0; e < 4; e++) acc[i][j][e] = 0.f;

        const int brow  = wn * 16 + ((lid >> 4) << 3) + (lid & 7);
        const int bcsel = (lid >> 3) & 1;
        const int acsel = lid >> 4;
#pragma unroll
        for (int ks = 0; ks < 2; ks++) {
            uint32_t bh[4], bl[4];
            const uint32_t baddr = sb + 8192 + brow * 64
                + (((2 * ks + bcsel) + ((brow >> 1) & 3)) & 3) * 16;
            LDSM4(bh, baddr);
            LDSM4(bl, baddr + 4096);
#pragma unroll
            for (int mi = 0; mi < 2; mi++) {
                const int arow = wm * 32 + mi * 16 + (lid & 15);
                const uint32_t aaddr = sb + arow * 64
                    + (((2 * ks + acsel) + ((arow >> 1) & 3)) & 3) * 16;
                uint32_t ah[4], al[4];
                LDSM4(ah, aaddr);
                LDSM4(al, aaddr + 4096);
#pragma unroll
                for (int nj = 0; nj < 2; nj++) {
                    MMA16816(acc[mi][nj], ah, bh[nj * 2], bh[nj * 2 + 1]);
                    MMA16816(acc[mi][nj], ah, bl[nj * 2], bl[nj * 2 + 1]);
                    MMA16816(acc[mi][nj], al, bh[nj * 2], bh[nj * 2 + 1]);
                }
            }
        }

        // epilogue: + precomputed bias table (float2), pads handled inline
        const float* bt = bias_tab
            + ((size_t)((b & (NWIN - 1)) * NHEAD + h)) * (NTOK * BT_ROW);
        const int r4 = lid >> 2, c2 = (lid & 3) * 2;
#pragma unroll
        for (int mi = 0; mi < 2; mi++)
#pragma unroll
            for (int nj = 0; nj < 2; nj++) {
                const int c0 = wn * 16 + nj * 8 + c2;
#pragma unroll
                for (int half = 0; half < 2; half++) {
                    const int n = wm * 32 + mi * 16 + r4 + half * 8;
                    float2 o;
                    if (n < NTOK) {
                        const float2 bv = *(const float2*)&bt[n * BT_ROW + c0];
                        o.x = (c0     < NTOK) ? acc[mi][nj][half * 2]     + bv.x
                                              : -3.0e38f;
                        o.y = (c0 + 1 < NTOK) ? acc[mi][nj][half * 2 + 1] + bv.y
                                              : -3.0e38f;
                    } else {
                        o.x = 0.f; o.y = 0.f;
                    }
                    *(float2*)&sc[n * 68 + c0] = o;
                }
            }
    }
    __syncthreads();

    // --- softmax: warp per row over 64 cols (8 warps) ---
    for (int r = wid; r < NTOK; r += 8) {
        float v0 = sc[r * 68 + lid];
        float v1 = sc[r * 68 + lid + 32];
        float mx = fmaxf(v0, v1);
#pragma unroll
        for (int o = 16; o; o >>= 1) mx = fmaxf(mx, __shfl_xor_sync(~0u, mx, o));
        float e0 = __expf(v0 - mx);
        float e1 = __expf(v1 - mx);
        float s = e0 + e1;
#pragma unroll
        for (int o = 16; o; o >>= 1) s += __shfl_xor_sync(~0u, s, o);
        const float inv = 1.f / s;
        sc[r * 68 + lid]      = e0 * inv;
        sc[r * 68 + lid + 32] = e1 * inv;
    }
    __syncthreads();

    // --- convert P -> split bf16 (reuses q/k region) ---
    for (int idx = tid; idx < 64 * 8; idx += 256) {
        const int n = idx >> 3;
        const int c = idx & 7;
        const float* s = sc + n * 68 + c * 8;
        uint32_t h0, l0, h1, l1, h2, l2, h3, l3;
        cvt_pair(s[0], s[1], h0, l0);
        cvt_pair(s[2], s[3], h1, l1);
        cvt_pair(s[4], s[5], h2, l2);
        cvt_pair(s[6], s[7], h3, l3);
        const uint32_t off = n * 128 + ((c + n) & 7) * 16;
        *(uint4*)(smA + off)        = make_uint4(h0, h1, h2, h3);
        *(uint4*)(smA + 8192 + off) = make_uint4(l0, l1, l2, l3);
    }
    __syncthreads();

    // --- phase2: O = P @ V  (M=64, N=32, K=64), warp tile 16x16 ---
    {
        const int wm = wid & 3;
        const int wn = wid >> 2;
        float acc[2][4];
#pragma unroll
        for (int j = 0; j < 2; j++)
#pragma unroll
            for (int e = 0; e < 4; e++) acc[j][e] = 0.f;

        const int arow  = wm * 16 + (lid & 15);
        const int acsel = lid >> 4;
        const int brow  = wn * 16 + ((lid >> 4) << 3) + (lid & 7);
        const int bcsel = (lid >> 3) & 1;
#pragma unroll
        for (int ks = 0; ks < 4; ks++) {
            uint32_t ah[4], al[4], bh[4], bl[4];
            const uint32_t aaddr = sb + arow * 128
                + (((2 * ks + acsel) + arow) & 7) * 16;
            LDSM4(ah, aaddr);
            LDSM4(al, aaddr + 8192);
            const uint32_t baddr = sb + 16384 + brow * 128
                + (((2 * ks + bcsel) + brow) & 7) * 16;
            LDSM4(bh, baddr);
            LDSM4(bl, baddr + 4096);
#pragma unroll
            for (int nj = 0; nj < 2; nj++) {
                MMA16816(acc[nj], ah, bh[nj * 2], bh[nj * 2 + 1]);
                MMA16816(acc[nj], ah, bl[nj * 2], bl[nj * 2 + 1]);
                MMA16816(acc[nj], al, bh[nj * 2], bh[nj * 2 + 1]);
            }
        }

        const int r4 = lid >> 2, c2 = (lid & 3) * 2;
#pragma unroll
        for (int nj = 0; nj < 2; nj++)
#pragma unroll
            for (int half = 0; half < 2; half++) {
                const int n = wm * 16 + r4 + half * 8;
                if (n < NTOK) {
                    const int d = wn * 16 + nj * 8 + c2;
                    const size_t o = (size_t)(b * NTOK + n) * CDIM
                                   + h * HDIM + d;
                    uint32_t hp, lp;
                    cvt_pair(acc[nj][half * 2], acc[nj][half * 2 + 1], hp, lp);
                    *(uint32_t*)(aoh + o) = hp;
                    *(uint32_t*)(aol + o) = lp;
                }
            }
    }
}

// ---------------------------------------------------------------------------
extern "C" void kernel_launch(void* const* d_in, const int* in_sizes, int n_in,
                              void* d_out, int out_size)
{
    const float* x      = (const float*)d_in[0];
    const float* mask   = (const float*)d_in[1];
    const float* rpb    = (const float*)d_in[2];
    const float* qkv_w  = (const float*)d_in[3];
    const float* qkv_b  = (const float*)d_in[4];
    const float* proj_w = (const float*)d_in[5];
    const float* proj_b = (const float*)d_in[6];
    float* out = (float*)d_out;

    float *qkv_ptr = nullptr, *bias_ptr = nullptr;
    __nv_bfloat16 *xh, *xl, *aoh, *aol, *wqh, *wql, *wph, *wpl;
    cudaGetSymbolAddress((void**)&qkv_ptr, g_qkv);
    cudaGetSymbolAddress((void**)&bias_ptr, g_bias);
    cudaGetSymbolAddress((void**)&xh,  g_xh);
    cudaGetSymbolAddress((void**)&xl,  g_xl);
    cudaGetSymbolAddress((void**)&aoh, g_aoh);
    cudaGetSymbolAddress((void**)&aol, g_aol);
    cudaGetSymbolAddress((void**)&wqh, g_wqh);
    cudaGetSymbolAddress((void**)&wql, g_wql);
    cudaGetSymbolAddress((void**)&wph, g_wph);
    cudaGetSymbolAddress((void**)&wpl, g_wpl);

    static bool cfg = false;
    if (!cfg) {
        cudaFuncSetAttribute(hmma_gemm, cudaFuncAttributeMaxDynamicSharedMemorySize,
                             SMEM_GEMM);
        cfg = true;
    }

    {
        int n4 = (M_ROWS * CDIM) / 4;
        split_bf16_kernel<<<(n4 + 255) / 256, 256>>>(
            (const float4*)x, (uint2*)xh, (uint2*)xl, n4);
        n4 = (3 * CDIM * CDIM) / 4;
        split_bf16_kernel<<<(n4 + 255) / 256, 256>>>(
            (const float4*)qkv_w, (uint2*)wqh, (uint2*)wql, n4);
        n4 = (CDIM * CDIM) / 4;
        split_bf16_kernel<<<(n4 + 255) / 256, 256>>>(
            (const float4*)proj_w, (uint2*)wph, (uint2*)wpl, n4);
        const int bt_total = NWIN * NHEAD * NTOK * BT_ROW;
        build_bias_kernel<<<(bt_total + 255) / 256, 256>>>(mask, rpb, bias_ptr);
    }

    hmma_gemm<<<dim3((3 * CDIM) / 128, M_ROWS / 128), 256, SMEM_GEMM>>>(
        xh, xl, wqh, wql, qkv_b, qkv_ptr, 3 * CDIM, CDIM);

    window_attn_hmma<<<B_TOT * NHEAD, 256>>>(qkv_ptr, bias_ptr, aoh, aol);

    hmma_gemm<<<dim3(CDIM / 128, M_ROWS / 128), 256, SMEM_GEMM>>>(
        aoh, aol, wph, wpl, proj_b, out, CDIM, CDIM);
}